// round 6
// baseline (speedup 1.0000x reference)
#include <cuda_runtime.h>

#define BSZ   4096
#define NNODE 16
#define OBSP  10
#define HID   128
#define GPB   2      // graphs per CTA (two warps each)
#define NTH   128

typedef unsigned long long ull;

// ---- packed f32x2 helpers (sm_103a; ptxas never auto-fuses these) ----
__device__ __forceinline__ ull pk2(float lo, float hi) {
    ull r; asm("mov.b64 %0, {%1, %2};" : "=l"(r) : "f"(lo), "f"(hi)); return r;
}
__device__ __forceinline__ void upk2(ull v, float& lo, float& hi) {
    asm("mov.b64 {%0, %1}, %2;" : "=f"(lo), "=f"(hi) : "l"(v));
}
__device__ __forceinline__ void ffma2(ull& d, ull a, ull b) {
    asm("fma.rn.f32x2 %0, %1, %2, %0;" : "+l"(d) : "l"(a), "l"(b));
}
__device__ __forceinline__ void add2(ull& d, ull a) {
    asm("add.rn.f32x2 %0, %0, %1;" : "+l"(d) : "l"(a));
}

// Per-graph shared: 2480 floats = 9920 B; x2 graphs = 19840 B/CTA.
// 5 CTAs/SM -> 99.2KB smem (100KB tier) -> ~128KB L1D: W1 (64KB) resident.
struct __align__(16) GSh {
    float A[NNODE][NNODE];   // normalized adjacency (symmetric)
    float Xat[OBSP][NNODE];  // (A@X) transposed
    float y2s[NNODE];
    float HsY[HID * 16];     // union:
                             //  Hs: col-major h0; col c floats [c*16..c*16+16),
                             //      16B unit u stored at slot (u+(c>>2))&3
                             //  Ys: y1 row-major [j*128 + col]
                             //  scratch: Xt[10][16], lx, ly, dinv
};

__global__ void __launch_bounds__(NTH, 5)
gcn_fused6(const float* __restrict__ obs, const float* __restrict__ act,
           const float* __restrict__ Q1W0, const float* __restrict__ Q1b0,
           const float* __restrict__ Q1W1, const float* __restrict__ Q1b1,
           const float* __restrict__ Q1W2, const float* __restrict__ Q1b2,
           const float* __restrict__ Q2W0, const float* __restrict__ Q2b0,
           const float* __restrict__ Q2W1, const float* __restrict__ Q2b1,
           const float* __restrict__ Q2W2, const float* __restrict__ Q2b2,
           float* __restrict__ out)
{
    __shared__ GSh sh[GPB];
    const int warp = threadIdx.x >> 5;
    const int lane = threadIdx.x & 31;
    const int wg   = warp & 1;            // which half of the graph's rows
    const int rlo  = wg * 8;              // this warp owns node rows rlo..rlo+7
    const int wg2  = wg * 2;              // Hs unit base for these rows
    GSh& S = sh[warp >> 1];
    const int g = blockIdx.x * GPB + (warp >> 1);
    const int gtid = wg * 32 + lane;      // 0..63 within the graph pair

    // scratch aliases inside HsY (dead before any HsY use)
    float* Xt   = S.HsY;                  // [10][16]
    float* lx   = S.HsY + 160;
    float* ly   = S.HsY + 176;
    float* dinv = S.HsY + 192;

    // ---- features: loc = obs cols 0,1; x = obs cols 2..9 ++ action cols 0,1
    {
        const float* ob = obs + (size_t)g * (NNODE * OBSP);
        #pragma unroll
        for (int r = 0; r < 3; r++) {
            int idx = gtid + 64 * r;
            if (idx < NNODE * OBSP) {
                float v = ob[idx];
                int n = idx / OBSP, k = idx - n * OBSP;
                if (k == 0)      lx[n] = v;
                else if (k == 1) ly[n] = v;
                else             Xt[(k - 2) * NNODE + n] = v;
            }
        }
        if (gtid < NNODE * 2) {
            float v = act[(size_t)g * (NNODE * 2) + gtid];
            Xt[(8 + (gtid & 1)) * NNODE + (gtid >> 1)] = v;
        }
    }
    __syncthreads();

    // ---- adjacency w_ij = exp(-||loc_i - loc_j||); bitwise-symmetric
    #pragma unroll
    for (int r = 0; r < 4; r++) {
        int e = gtid * 4 + r, i = e >> 4, j = e & 15;
        float dx = lx[i] - lx[j], dy = ly[i] - ly[j];
        S.A[i][j] = expf(-sqrtf(dx * dx + dy * dy));
    }
    __syncthreads();
    if (gtid < NNODE) {
        float s = 0.f;
        #pragma unroll
        for (int j = 0; j < NNODE; j++) s += S.A[j][gtid];
        dinv[gtid] = rsqrtf(s);           // deg >= 1 (self loop)
    }
    __syncthreads();
    #pragma unroll
    for (int r = 0; r < 4; r++) {
        int e = gtid * 4 + r, i = e >> 4, j = e & 15;
        S.A[i][j] *= dinv[i] * dinv[j];
    }
    __syncthreads();

    // ---- Xa = A @ X (shared by both heads), stored transposed Xat[k][i]
    #pragma unroll
    for (int r = 0; r < 3; r++) {
        int idx = gtid + 64 * r;
        if (idx < NNODE * OBSP) {
            int i = idx / OBSP, k = idx - i * OBSP;
            float s = 0.f;
            #pragma unroll
            for (int j = 0; j < NNODE; j++) s = fmaf(S.A[i][j], Xt[k * NNODE + j], s);
            S.Xat[k][i] = s;
        }
    }
    __syncthreads();

    #pragma unroll 1
    for (int q = 0; q < 2; q++) {
        const float* W0 = q ? Q2W0 : Q1W0;
        const float* B0 = q ? Q2b0 : Q1b0;
        const float* W1 = q ? Q2W1 : Q1W1;
        const float* B1 = q ? Q2b1 : Q1b1;
        const float* W2 = q ? Q2W2 : Q1W2;
        const float* B2 = q ? Q2b2 : Q1b2;

        // lane owns cols 4*lane+{0..3}, rows rlo..rlo+7.
        // acc[c*4+m] = packed rows (rlo+2m, rlo+2m+1) of col 4*lane+c.
        ull acc[16];
        #pragma unroll
        for (int p = 0; p < 16; p++) acc[p] = 0ull;

        // ---- GEMM0 (pre-aggregated): h0 = relu(Xa @ W0 + b0)
        #pragma unroll
        for (int k = 0; k < OBSP; k++) {
            float4 w4 = __ldg(reinterpret_cast<const float4*>(W0 + k * HID) + lane);
            const ulonglong2* xr = reinterpret_cast<const ulonglong2*>(&S.Xat[k][rlo]);
            ulonglong2 xa = xr[0], xb = xr[1];
            ull r4[4] = {xa.x, xa.y, xb.x, xb.y};
            ull wd;
            wd = pk2(w4.x, w4.x);
            #pragma unroll
            for (int m = 0; m < 4; m++) ffma2(acc[m],      r4[m], wd);
            wd = pk2(w4.y, w4.y);
            #pragma unroll
            for (int m = 0; m < 4; m++) ffma2(acc[4 + m],  r4[m], wd);
            wd = pk2(w4.z, w4.z);
            #pragma unroll
            for (int m = 0; m < 4; m++) ffma2(acc[8 + m],  r4[m], wd);
            wd = pk2(w4.w, w4.w);
            #pragma unroll
            for (int m = 0; m < 4; m++) ffma2(acc[12 + m], r4[m], wd);
        }
        // epilogue: h0 rows rlo..+7 -> Hs (swizzled col-major)
        {
            float4 b0v = __ldg(reinterpret_cast<const float4*>(B0) + lane);
            float bc[4] = {b0v.x, b0v.y, b0v.z, b0v.w};
            #pragma unroll
            for (int c = 0; c < 4; c++) {
                float4* dst = reinterpret_cast<float4*>(&S.HsY[(4 * lane + c) * 16]);
                float h0_, h1_, h2_, h3_, h4_, h5_, h6_, h7_;
                upk2(acc[c * 4 + 0], h0_, h1_);
                upk2(acc[c * 4 + 1], h2_, h3_);
                upk2(acc[c * 4 + 2], h4_, h5_);
                upk2(acc[c * 4 + 3], h6_, h7_);
                dst[(wg2 + lane) & 3] =
                    make_float4(fmaxf(h0_ + bc[c], 0.f), fmaxf(h1_ + bc[c], 0.f),
                                fmaxf(h2_ + bc[c], 0.f), fmaxf(h3_ + bc[c], 0.f));
                dst[(wg2 + 1 + lane) & 3] =
                    make_float4(fmaxf(h4_ + bc[c], 0.f), fmaxf(h5_ + bc[c], 0.f),
                                fmaxf(h6_ + bc[c], 0.f), fmaxf(h7_ + bc[c], 0.f));
            }
        }
        __syncwarp();   // warp reads only its own rows (written by its own lanes)

        // ---- GEMM1 (dominant): y1[rows rlo..+7] = h0 @ W1
        #pragma unroll
        for (int p = 0; p < 16; p++) acc[p] = 0ull;
        {
            const float4* W1v = reinterpret_cast<const float4*>(W1) + lane;
            #pragma unroll 1
            for (int kb = 0; kb < HID; kb += 16) {
                #pragma unroll
                for (int s = 0; s < 16; s++) {
                    const int k = kb + s;
                    const int r = (s >> 2) & 3;          // compile-time rotation
                    float4 w4 = __ldg(W1v + k * (HID / 4));
                    const ulonglong2* unit =
                        reinterpret_cast<const ulonglong2*>(&S.HsY[k * 16]);
                    ulonglong2 d0 = unit[(wg2 + r) & 3];       // rows rlo..+3
                    ulonglong2 d1 = unit[(wg2 + 1 + r) & 3];   // rows rlo+4..+7
                    ull r4[4] = {d0.x, d0.y, d1.x, d1.y};
                    ull wd;
                    wd = pk2(w4.x, w4.x);
                    #pragma unroll
                    for (int m = 0; m < 4; m++) ffma2(acc[m],      r4[m], wd);
                    wd = pk2(w4.y, w4.y);
                    #pragma unroll
                    for (int m = 0; m < 4; m++) ffma2(acc[4 + m],  r4[m], wd);
                    wd = pk2(w4.z, w4.z);
                    #pragma unroll
                    for (int m = 0; m < 4; m++) ffma2(acc[8 + m],  r4[m], wd);
                    wd = pk2(w4.w, w4.w);
                    #pragma unroll
                    for (int m = 0; m < 4; m++) ffma2(acc[12 + m], r4[m], wd);
                }
            }
        }
        __syncthreads();   // Ys write below aliases the OTHER warp's Hs region

        // ---- y1 -> Ys row-major (aliases dead h0): Ys[j][col], stride 128
        #pragma unroll
        for (int m = 0; m < 4; m++) {
            float a0, a1, b0_, b1_, c0, c1, d0, d1;
            upk2(acc[m],      a0, a1);   // col 4l+0, rows rlo+2m / +2m+1
            upk2(acc[4 + m],  b0_, b1_);
            upk2(acc[8 + m],  c0, c1);
            upk2(acc[12 + m], d0, d1);
            *reinterpret_cast<float4*>(&S.HsY[(rlo + 2 * m) * HID + 4 * lane])
                = make_float4(a0, b0_, c0, d0);
            *reinterpret_cast<float4*>(&S.HsY[(rlo + 2 * m + 1) * HID + 4 * lane])
                = make_float4(a1, b1_, c1, d1);
        }
        __syncthreads();   // agg1 needs ALL 16 rows (both warps)

        // ---- agg1 = A @ y1 for out rows rlo..+7, cols 4*lane+{0..3}
        ull acc2[16];
        #pragma unroll
        for (int p = 0; p < 16; p++) acc2[p] = 0ull;
        #pragma unroll
        for (int j = 0; j < NNODE; j++) {
            float4 y4 = *reinterpret_cast<const float4*>(&S.HsY[j * HID + 4 * lane]);
            const ulonglong2* ar2 = reinterpret_cast<const ulonglong2*>(&S.A[j][rlo]);
            ulonglong2 aa = ar2[0], ab = ar2[1];    // A[i][j]=A[j][i], rows rlo..+7
            ull ar[4] = {aa.x, aa.y, ab.x, ab.y};
            ull yd;
            yd = pk2(y4.x, y4.x);
            #pragma unroll
            for (int m = 0; m < 4; m++) ffma2(acc2[m],      ar[m], yd);
            yd = pk2(y4.y, y4.y);
            #pragma unroll
            for (int m = 0; m < 4; m++) ffma2(acc2[4 + m],  ar[m], yd);
            yd = pk2(y4.z, y4.z);
            #pragma unroll
            for (int m = 0; m < 4; m++) ffma2(acc2[8 + m],  ar[m], yd);
            yd = pk2(y4.w, y4.w);
            #pragma unroll
            for (int m = 0; m < 4; m++) ffma2(acc2[12 + m], ar[m], yd);
        }

        // ---- h1 = relu(acc2 + b1); part[m] = rows: sum_c h1 * W2[col]
        ull part[4];
        #pragma unroll
        for (int m = 0; m < 4; m++) part[m] = 0ull;
        {
            float4 b1v = __ldg(reinterpret_cast<const float4*>(B1) + lane);
            float4 w2v = __ldg(reinterpret_cast<const float4*>(W2) + lane);
            float bc[4] = {b1v.x, b1v.y, b1v.z, b1v.w};
            float wc[4] = {w2v.x, w2v.y, w2v.z, w2v.w};
            #pragma unroll
            for (int c = 0; c < 4; c++) {
                ull w2d = pk2(wc[c], wc[c]);
                #pragma unroll
                for (int m = 0; m < 4; m++) {
                    float lo, hi; upk2(acc2[c * 4 + m], lo, hi);
                    lo = fmaxf(lo + bc[c], 0.f);
                    hi = fmaxf(hi + bc[c], 0.f);
                    ffma2(part[m], pk2(lo, hi), w2d);
                }
            }
        }

        // ---- warp-xor reduce (sums this warp's 128 cols); rows rlo..+7 done
        #pragma unroll
        for (int off = 16; off > 0; off >>= 1) {
            #pragma unroll
            for (int m = 0; m < 4; m++) {
                ull o = __shfl_xor_sync(0xffffffffu, part[m], off);
                add2(part[m], o);
            }
        }
        if (lane == 0) {   // publish this warp's 8 y2 values
            *reinterpret_cast<ull*>(&S.y2s[rlo + 0]) = part[0];
            *reinterpret_cast<ull*>(&S.y2s[rlo + 2]) = part[1];
            *reinterpret_cast<ull*>(&S.y2s[rlo + 4]) = part[2];
            *reinterpret_cast<ull*>(&S.y2s[rlo + 6]) = part[3];
        }
        __syncthreads();   // both halves of y2 visible

        // ---- out[i] = b2 + sum_j A[i][j] * y2[j]; warp covers rows rlo..+7
        if (lane < 8) {
            int i = rlo + lane;
            float o = __ldg(B2);
            #pragma unroll
            for (int j = 0; j < NNODE; j++)
                o = fmaf(S.A[j][i], S.y2s[j], o);
            out[(size_t)q * BSZ * NNODE + (size_t)g * NNODE + i] = o;
        }
        __syncthreads();   // before next head overwrites HsY / y2s
    }
}

extern "C" void kernel_launch(void* const* d_in, const int* in_sizes, int n_in,
                              void* d_out, int out_size)
{
    (void)in_sizes; (void)n_in; (void)out_size;
    // ~44% carveout -> 100KB smem tier (5 CTAs x 19.84KB), ~128KB L1D for W1.
    cudaFuncSetAttribute(gcn_fused6,
                         cudaFuncAttributePreferredSharedMemoryCarveout, 44);
    gcn_fused6<<<BSZ / GPB, NTH>>>(
        (const float*)d_in[0],  (const float*)d_in[1],
        (const float*)d_in[2],  (const float*)d_in[3],
        (const float*)d_in[4],  (const float*)d_in[5],
        (const float*)d_in[6],  (const float*)d_in[7],
        (const float*)d_in[8],  (const float*)d_in[9],
        (const float*)d_in[10], (const float*)d_in[11],
        (const float*)d_in[12], (const float*)d_in[13],
        (float*)d_out);
}

// round 8
// speedup vs baseline: 1.0048x; 1.0048x over previous
#include <cuda_runtime.h>
#include <cstdint>

#define BSZ   4096
#define NNODE 16
#define OBSP  10
#define HID   128
#define GPB   8          // graphs per CTA (one warp each)
#define NTH   256

typedef unsigned long long ull;
typedef unsigned int u32;

// ---------------- SMEM layout (dynamic, byte offsets) ----------------
// B buffers: W1^T bf16 [128 n][136 k-pad] rows of 272B (16B aligned, 4-bank row shift)
#define BROW    272
#define BBYTES  (HID * BROW)                  // 34816
#define OFF_BH1 0
#define OFF_BL1 (OFF_BH1 + BBYTES)
#define OFF_BH2 (OFF_BL1 + BBYTES)
#define OFF_BL2 (OFF_BH2 + BBYTES)
#define OFF_AREG (OFF_BL2 + BBYTES)           // 139264
#define AREG_SZ  8704                         // per graph: Ahi[16][136]bf16 + Alo
                                              // alias: Ys fp32 [16][132] (8448B)
                                              // alias(setup): W1s fp32 [128][132] spans all 8
#define OFF_GS   (OFF_AREG + GPB * AREG_SZ)   // 208896
#define GS_SZ    1664                         // A[16][16] + Xat[10][16] floats
#define SMEM_TOTAL (OFF_GS + GPB * GS_SZ)     // 222208

// ---------------- mma.sync / ldmatrix helpers (sm_80+ portable) ----------------
#define LDSM_X4(r, addr) \
    asm volatile("ldmatrix.sync.aligned.m8n8.x4.shared.b16 {%0,%1,%2,%3}, [%4];" \
        : "=r"((r)[0]), "=r"((r)[1]), "=r"((r)[2]), "=r"((r)[3]) : "r"(addr))

#define MMA_BF16(d, a, b0, b1) \
    asm volatile("mma.sync.aligned.m16n8k16.row.col.f32.bf16.bf16.f32 " \
        "{%0,%1,%2,%3}, {%4,%5,%6,%7}, {%8,%9}, {%0,%1,%2,%3};" \
        : "+f"((d)[0]), "+f"((d)[1]), "+f"((d)[2]), "+f"((d)[3]) \
        : "r"((a)[0]), "r"((a)[1]), "r"((a)[2]), "r"((a)[3]), "r"(b0), "r"(b1))

__device__ __forceinline__ u32 smem_u32(const void* p) {
    u32 a;
    asm("{ .reg .u64 t; cvta.to.shared.u64 t, %1; cvt.u32.u64 %0, t; }" : "=r"(a) : "l"(p));
    return a;
}

// ---- packed f32x2 + bf16 helpers ----
__device__ __forceinline__ ull pk2(float lo, float hi) {
    ull r; asm("mov.b64 %0, {%1, %2};" : "=l"(r) : "f"(lo), "f"(hi)); return r;
}
__device__ __forceinline__ void upk2(ull v, float& lo, float& hi) {
    asm("mov.b64 {%0, %1}, %2;" : "=f"(lo), "=f"(hi) : "l"(v));
}
__device__ __forceinline__ void ffma2(ull& d, ull a, ull b) {
    asm("fma.rn.f32x2 %0, %1, %2, %0;" : "+l"(d) : "l"(a), "l"(b));
}
__device__ __forceinline__ void add2(ull& d, ull a) {
    asm("add.rn.f32x2 %0, %0, %1;" : "+l"(d) : "l"(a));
}
__device__ __forceinline__ u32 packbf(float hi_el, float lo_el) {   // hi->upper, lo->lower
    u32 r; asm("cvt.rn.bf16x2.f32 %0, %1, %2;" : "=r"(r) : "f"(hi_el), "f"(lo_el));
    return r;
}
__device__ __forceinline__ float bf_lo(u32 w) { return __uint_as_float(w << 16); }
__device__ __forceinline__ float bf_hi(u32 w) { return __uint_as_float(w & 0xffff0000u); }

struct __align__(16) GS {
    float A[NNODE][NNODE];     // normalized adjacency (symmetric)
    float Xat[OBSP][NNODE];    // (A@X) transposed
};

#define LOADROW8(dst, ptr) do { \
    const ulonglong2* _p = reinterpret_cast<const ulonglong2*>(ptr); \
    ulonglong2 _a = _p[0], _b = _p[1], _c = _p[2], _d = _p[3]; \
    dst[0]=_a.x; dst[1]=_a.y; dst[2]=_b.x; dst[3]=_b.y; \
    dst[4]=_c.x; dst[5]=_c.y; dst[6]=_d.x; dst[7]=_d.y; } while(0)

__global__ void __launch_bounds__(NTH, 1)
gcn_mma(const float* __restrict__ obs, const float* __restrict__ act,
        const float* __restrict__ Q1W0, const float* __restrict__ Q1b0,
        const float* __restrict__ Q1W1, const float* __restrict__ Q1b1,
        const float* __restrict__ Q1W2, const float* __restrict__ Q1b2,
        const float* __restrict__ Q2W0, const float* __restrict__ Q2b0,
        const float* __restrict__ Q2W1, const float* __restrict__ Q2b1,
        const float* __restrict__ Q2W2, const float* __restrict__ Q2b2,
        float* __restrict__ out)
{
    extern __shared__ __align__(16) char smem[];
    const int tid  = threadIdx.x;
    const int warp = tid >> 5;            // 0..7 == graph within CTA
    const int lane = tid & 31;
    const u32 sb   = smem_u32(smem);

    GS* G = reinterpret_cast<GS*>(smem + OFF_GS + warp * GS_SZ);
    char* GA = smem + OFF_AREG + warp * AREG_SZ;      // per-graph Ahi/Alo/Ys
    const int g = blockIdx.x * GPB + warp;

    // ---- per-graph preamble (warp-private); Xt/lx/ly/dinv scratch in own A-region
    {
        float* Xt   = reinterpret_cast<float*>(GA);
        float* lx   = Xt + 160;
        float* ly   = Xt + 176;
        float* dinv = Xt + 192;
        const float* ob = obs + (size_t)g * (NNODE * OBSP);
        #pragma unroll
        for (int r = 0; r < 5; r++) {
            int idx = lane + 32 * r;
            float v = ob[idx];
            int n = idx / OBSP, k = idx - n * OBSP;
            if (k == 0)      lx[n] = v;
            else if (k == 1) ly[n] = v;
            else             Xt[(k - 2) * NNODE + n] = v;
        }
        float v = act[(size_t)g * (NNODE * 2) + lane];
        Xt[(8 + (lane & 1)) * NNODE + (lane >> 1)] = v;
        __syncwarp();
        #pragma unroll
        for (int r = 0; r < 8; r++) {
            int e = lane * 8 + r, i = e >> 4, j = e & 15;
            float dx = lx[i] - lx[j], dy = ly[i] - ly[j];
            G->A[i][j] = expf(-sqrtf(dx * dx + dy * dy));
        }
        __syncwarp();
        if (lane < NNODE) {
            float s = 0.f;
            #pragma unroll
            for (int j = 0; j < NNODE; j++) s += G->A[j][lane];
            dinv[lane] = rsqrtf(s);               // deg >= 1 (self loop)
        }
        __syncwarp();
        #pragma unroll
        for (int r = 0; r < 8; r++) {
            int e = lane * 8 + r, i = e >> 4, j = e & 15;
            G->A[i][j] *= dinv[i] * dinv[j];
        }
        __syncwarp();
        #pragma unroll
        for (int r = 0; r < 5; r++) {
            int idx = lane + 32 * r;              // 160 = 16 x 10
            int i = idx / OBSP, k = idx - i * OBSP;
            float s = 0.f;
            #pragma unroll
            for (int j = 0; j < NNODE; j++) s = fmaf(G->A[i][j], Xt[k * NNODE + j], s);
            G->Xat[k][i] = s;
        }
    }
    __syncthreads();   // scratch dead; A-region becomes W1 fp32 staging

    // ---- stage W1 (both heads) -> bf16 hi/lo B buffers, W1^T [n][k] pad-272B rows
    {
        float* W1s = reinterpret_cast<float*>(smem + OFF_AREG);   // [128][132]
        #pragma unroll 1
        for (int h = 0; h < 2; h++) {
            const float* W1 = h ? Q2W1 : Q1W1;
            #pragma unroll 8
            for (int i = tid; i < HID * HID; i += NTH)
                W1s[(i >> 7) * 132 + (i & 127)] = __ldg(W1 + i);
            __syncthreads();
            char* BH = smem + (h ? OFF_BH2 : OFF_BH1);
            char* BL = smem + (h ? OFF_BL2 : OFF_BL1);
            const int n  = tid >> 1;
            const int k0 = (tid & 1) * 64;
            #pragma unroll
            for (int kb = 0; kb < 64; kb += 8) {
                float f[8];
                #pragma unroll
                for (int j = 0; j < 8; j++) f[j] = W1s[(k0 + kb + j) * 132 + n];
                u32 hw[4], lw[4];
                #pragma unroll
                for (int p = 0; p < 4; p++) {
                    hw[p] = packbf(f[2 * p + 1], f[2 * p]);
                    lw[p] = packbf(f[2 * p + 1] - bf_hi(hw[p]),
                                   f[2 * p]     - bf_lo(hw[p]));
                }
                *reinterpret_cast<uint4*>(BH + n * BROW + (k0 + kb) * 2) =
                    make_uint4(hw[0], hw[1], hw[2], hw[3]);
                *reinterpret_cast<uint4*>(BL + n * BROW + (k0 + kb) * 2) =
                    make_uint4(lw[0], lw[1], lw[2], lw[3]);
            }
            __syncthreads();   // W1s reusable for next head
        }
    }
    // From here: everything is warp-private (+ read-only B). No CTA barriers.

    const u32 GAhi = sb + (u32)(OFF_AREG + warp * AREG_SZ);
    const u32 GAlo = GAhi + 4352;
    float* Ys = reinterpret_cast<float*>(GA);      // fp32 [16][132], aliases Ahi/Alo

    #pragma unroll 1
    for (int q = 0; q < 2; q++) {
        const float* W0 = q ? Q2W0 : Q1W0;
        const float* B0 = q ? Q2b0 : Q1b0;
        const float* B1 = q ? Q2b1 : Q1b1;
        const float* W2 = q ? Q2W2 : Q1W2;
        const float* B2 = q ? Q2b2 : Q1b2;
        const u32 BHq = sb + (u32)(q ? OFF_BH2 : OFF_BH1);
        const u32 BLq = sb + (u32)(q ? OFF_BL2 : OFF_BL1);

        // ==== GEMM0 (scalar fp32): y0 = Xa @ W0; relu(+b0) -> Ahi/Alo bf16
        {
            ull acc[32];
            #pragma unroll
            for (int p = 0; p < 32; p++) acc[p] = 0ull;
            #pragma unroll
            for (int k = 0; k < OBSP; k++) {
                float4 w4 = __ldg(reinterpret_cast<const float4*>(W0 + k * HID) + lane);
                ull row[8]; LOADROW8(row, &G->Xat[k][0]);
                ull wd;
                wd = pk2(w4.x, w4.x);
                #pragma unroll
                for (int m = 0; m < 8; m++) ffma2(acc[m],      row[m], wd);
                wd = pk2(w4.y, w4.y);
                #pragma unroll
                for (int m = 0; m < 8; m++) ffma2(acc[8 + m],  row[m], wd);
                wd = pk2(w4.z, w4.z);
                #pragma unroll
                for (int m = 0; m < 8; m++) ffma2(acc[16 + m], row[m], wd);
                wd = pk2(w4.w, w4.w);
                #pragma unroll
                for (int m = 0; m < 8; m++) ffma2(acc[24 + m], row[m], wd);
            }
            __syncwarp();   // prior-phase Ys reads (q==1) done before overwrite
            float4 b0v = __ldg(reinterpret_cast<const float4*>(B0) + lane);
            float bc[4] = {b0v.x, b0v.y, b0v.z, b0v.w};
            #pragma unroll
            for (int m = 0; m < 8; m++) {
                float va[4], vb[4];
                #pragma unroll
                for (int c = 0; c < 4; c++) upk2(acc[c * 8 + m], va[c], vb[c]);
                #pragma unroll
                for (int rr = 0; rr < 2; rr++) {
                    const float* v = rr ? vb : va;
                    int row = 2 * m + rr;
                    float h0 = fmaxf(v[0] + bc[0], 0.f), h1 = fmaxf(v[1] + bc[1], 0.f);
                    float h2 = fmaxf(v[2] + bc[2], 0.f), h3 = fmaxf(v[3] + bc[3], 0.f);
                    u32 p0 = packbf(h1, h0), p1 = packbf(h3, h2);
                    u32 q0 = packbf(h1 - bf_hi(p0), h0 - bf_lo(p0));
                    u32 q1 = packbf(h3 - bf_hi(p1), h2 - bf_lo(p1));
                    *reinterpret_cast<uint2*>(smem + (GAhi - sb) + row * BROW + lane * 8)
                        = make_uint2(p0, p1);
                    *reinterpret_cast<uint2*>(smem + (GAlo - sb) + row * BROW + lane * 8)
                        = make_uint2(q0, q1);
                }
            }
        }
        __syncwarp();

        // ==== GEMM1 (tensor): y1 = h0 @ W1 via mma.m16n8k16 bf16, 3-term split
        {
            // A fragments for all 8 k-steps (hi and lo)
            u32 ah[8][4], al[8][4];
            const u32 arow = (u32)(lane & 15) * BROW + (u32)(lane >> 4) * 16;
            #pragma unroll
            for (int ks = 0; ks < 8; ks++) {
                LDSM_X4(ah[ks], GAhi + arow + ks * 32);
                LDSM_X4(al[ks], GAlo + arow + ks * 32);
            }
            const u32 brow = (u32)(lane & 15) * BROW + (u32)(lane >> 4) * 16;
            const int gid = lane >> 2, tig = lane & 3;

            #pragma unroll 1
            for (int np = 0; np < 8; np++) {
                float dA0[4] = {0,0,0,0}, dB0[4] = {0,0,0,0}, dC0[4] = {0,0,0,0};
                float dA1[4] = {0,0,0,0}, dB1[4] = {0,0,0,0}, dC1[4] = {0,0,0,0};
                const u32 bhb = BHq + (u32)(16 * np) * BROW + brow;
                const u32 blb = BLq + (u32)(16 * np) * BROW + brow;
                #pragma unroll
                for (int ks = 0; ks < 8; ks++) {
                    u32 bb[4]; LDSM_X4(bb, bhb + ks * 32);
                    MMA_BF16(dA0, ah[ks], bb[0], bb[2]);
                    MMA_BF16(dB0, al[ks], bb[0], bb[2]);
                    MMA_BF16(dA1, ah[ks], bb[1], bb[3]);
                    MMA_BF16(dB1, al[ks], bb[1], bb[3]);
                }
                #pragma unroll
                for (int ks = 0; ks < 8; ks++) {
                    u32 bb[4]; LDSM_X4(bb, blb + ks * 32);
                    MMA_BF16(dC0, ah[ks], bb[0], bb[2]);
                    MMA_BF16(dC1, ah[ks], bb[1], bb[3]);
                }
                // combine + store to Ys (fp32); cols 16np + {0..7} and {8..15}
                #pragma unroll
                for (int t2 = 0; t2 < 2; t2++) {
                    float* dA = t2 ? dA1 : dA0;
                    float* dB = t2 ? dB1 : dB0;
                    float* dC = t2 ? dC1 : dC0;
                    int col = 16 * np + 8 * t2 + 2 * tig;
                    float s0 = dA[0] + dB[0] + dC[0];
                    float s1 = dA[1] + dB[1] + dC[1];
                    float s2 = dA[2] + dB[2] + dC[2];
                    float s3 = dA[3] + dB[3] + dC[3];
                    *reinterpret_cast<float2*>(&Ys[gid * 132 + col])       // A frags
                        = make_float2(s0, s1);                             // consumed;
                    *reinterpret_cast<float2*>(&Ys[(gid + 8) * 132 + col]) // alias OK
                        = make_float2(s2, s3);
                }
            }
        }
        __syncwarp();

        // ==== agg1 = A @ y1; relu(+b1); fused layer-2 partial; reduce; final agg
        {
            ull acc2[32];
            #pragma unroll
            for (int p = 0; p < 32; p++) acc2[p] = 0ull;
            #pragma unroll 4
            for (int j = 0; j < NNODE; j++) {
                float4 y4 = *reinterpret_cast<const float4*>(&Ys[j * 132 + 4 * lane]);
                ull ar[8]; LOADROW8(ar, &G->A[j][0]);
                ull yd;
                yd = pk2(y4.x, y4.x);
                #pragma unroll
                for (int m = 0; m < 8; m++) ffma2(acc2[m],      ar[m], yd);
                yd = pk2(y4.y, y4.y);
                #pragma unroll
                for (int m = 0; m < 8; m++) ffma2(acc2[8 + m],  ar[m], yd);
                yd = pk2(y4.z, y4.z);
                #pragma unroll
                for (int m = 0; m < 8; m++) ffma2(acc2[16 + m], ar[m], yd);
                yd = pk2(y4.w, y4.w);
                #pragma unroll
                for (int m = 0; m < 8; m++) ffma2(acc2[24 + m], ar[m], yd);
            }
            ull part[8];
            #pragma unroll
            for (int m = 0; m < 8; m++) part[m] = 0ull;
            {
                float4 b1v = __ldg(reinterpret_cast<const float4*>(B1) + lane);
                float4 w2v = __ldg(reinterpret_cast<const float4*>(W2) + lane);
                float bc[4] = {b1v.x, b1v.y, b1v.z, b1v.w};
                float wc[4] = {w2v.x, w2v.y, w2v.z, w2v.w};
                #pragma unroll
                for (int c = 0; c < 4; c++) {
                    ull w2d = pk2(wc[c], wc[c]);
                    #pragma unroll
                    for (int m = 0; m < 8; m++) {
                        float lo, hi; upk2(acc2[c * 8 + m], lo, hi);
                        lo = fmaxf(lo + bc[c], 0.f);
                        hi = fmaxf(hi + bc[c], 0.f);
                        ffma2(part[m], pk2(lo, hi), w2d);
                    }
                }
            }
            #pragma unroll
            for (int off = 16; off > 0; off >>= 1) {
                #pragma unroll
                for (int m = 0; m < 8; m++) {
                    ull o = __shfl_xor_sync(0xffffffffu, part[m], off);
                    add2(part[m], o);
                }
            }
            if (lane < NNODE) {
                float y2[16];
                #pragma unroll
                for (int m = 0; m < 8; m++) upk2(part[m], y2[2 * m], y2[2 * m + 1]);
                float o = __ldg(B2);
                #pragma unroll
                for (int j = 0; j < NNODE; j++)
                    o = fmaf(G->A[j][lane], y2[j], o);
                out[(size_t)q * BSZ * NNODE + (size_t)g * NNODE + lane] = o;
            }
        }
        __syncwarp();   // Ys dead before next head's GEMM0 epilogue overwrites
    }
}

extern "C" void kernel_launch(void* const* d_in, const int* in_sizes, int n_in,
                              void* d_out, int out_size)
{
    (void)in_sizes; (void)n_in; (void)out_size;
    cudaFuncSetAttribute(gcn_mma, cudaFuncAttributeMaxDynamicSharedMemorySize, SMEM_TOTAL);
    gcn_mma<<<BSZ / GPB, NTH, SMEM_TOTAL>>>(
        (const float*)d_in[0],  (const float*)d_in[1],
        (const float*)d_in[2],  (const float*)d_in[3],
        (const float*)d_in[4],  (const float*)d_in[5],
        (const float*)d_in[6],  (const float*)d_in[7],
        (const float*)d_in[8],  (const float*)d_in[9],
        (const float*)d_in[10], (const float*)d_in[11],
        (const float*)d_in[12], (const float*)d_in[13],
        (float*)d_out);
}

// round 9
// speedup vs baseline: 1.5730x; 1.5655x over previous
#include <cuda_runtime.h>
#include <cstdint>

#define BSZ   4096
#define NNODE 16
#define OBSP  10
#define HID   128
#define GPB   4          // graphs per CTA (one warp each)
#define NTH   128
#define BROW  272        // A-tile row pitch in bytes (16 rows x 136 bf16)

typedef unsigned long long ull;
typedef unsigned int u32;

// ---- B fragments in gmem, exact mma operand order, built by prep kernel ----
// [head][np(16-col tile)][ks][lane] = {b0_t0, b1_t0, b0_t1, b1_t1}
__device__ uint4 g_bfragH[2][8][8][32];
__device__ uint4 g_bfragL[2][8][8][32];

// ---------------- mma.sync / ldmatrix (sm_80+ portable) ----------------
#define LDSM_X4(r, addr) \
    asm volatile("ldmatrix.sync.aligned.m8n8.x4.shared.b16 {%0,%1,%2,%3}, [%4];" \
        : "=r"((r)[0]), "=r"((r)[1]), "=r"((r)[2]), "=r"((r)[3]) : "r"(addr))
#define MMA_BF16(d, a, b0, b1) \
    asm volatile("mma.sync.aligned.m16n8k16.row.col.f32.bf16.bf16.f32 " \
        "{%0,%1,%2,%3}, {%4,%5,%6,%7}, {%8,%9}, {%0,%1,%2,%3};" \
        : "+f"((d)[0]), "+f"((d)[1]), "+f"((d)[2]), "+f"((d)[3]) \
        : "r"((a)[0]), "r"((a)[1]), "r"((a)[2]), "r"((a)[3]), "r"(b0), "r"(b1))

__device__ __forceinline__ u32 smem_u32(const void* p) {
    u32 a;
    asm("{ .reg .u64 t; cvta.to.shared.u64 t, %1; cvt.u32.u64 %0, t; }" : "=r"(a) : "l"(p));
    return a;
}
// ---- packed f32x2 + bf16 helpers ----
__device__ __forceinline__ ull pk2(float lo, float hi) {
    ull r; asm("mov.b64 %0, {%1, %2};" : "=l"(r) : "f"(lo), "f"(hi)); return r;
}
__device__ __forceinline__ void upk2(ull v, float& lo, float& hi) {
    asm("mov.b64 {%0, %1}, %2;" : "=f"(lo), "=f"(hi) : "l"(v));
}
__device__ __forceinline__ void ffma2(ull& d, ull a, ull b) {
    asm("fma.rn.f32x2 %0, %1, %2, %0;" : "+l"(d) : "l"(a), "l"(b));
}
__device__ __forceinline__ void add2(ull& d, ull a) {
    asm("add.rn.f32x2 %0, %0, %1;" : "+l"(d) : "l"(a));
}
__device__ __forceinline__ u32 packbf(float hi_el, float lo_el) {
    u32 r; asm("cvt.rn.bf16x2.f32 %0, %1, %2;" : "=r"(r) : "f"(hi_el), "f"(lo_el));
    return r;
}
__device__ __forceinline__ float bf_lo(u32 w) { return __uint_as_float(w << 16); }
__device__ __forceinline__ float bf_hi(u32 w) { return __uint_as_float(w & 0xffff0000u); }

// ---------------- pre-kernel: W1 -> bf16 hi/lo fragments ----------------
__global__ void __launch_bounds__(256)
prep_bfrag(const float* __restrict__ W1a, const float* __restrict__ W1b)
{
    int id = blockIdx.x * 256 + threadIdx.x;      // 0..4095
    int h  = id >> 11, np = (id >> 8) & 7, ks = (id >> 5) & 7, l = id & 31;
    const float* W1 = h ? W1b : W1a;
    int n0 = 16 * np + (l >> 2);
    int n1 = n0 + 8;
    int k0 = 16 * ks + (l & 3) * 2;
    float f00 = W1[k0 * HID + n0],       f01 = W1[(k0 + 1) * HID + n0];
    float f02 = W1[(k0 + 8) * HID + n0], f03 = W1[(k0 + 9) * HID + n0];
    float f10 = W1[k0 * HID + n1],       f11 = W1[(k0 + 1) * HID + n1];
    float f12 = W1[(k0 + 8) * HID + n1], f13 = W1[(k0 + 9) * HID + n1];
    u32 h0 = packbf(f01, f00), h1 = packbf(f03, f02);
    u32 h2 = packbf(f11, f10), h3 = packbf(f13, f12);
    u32 l0 = packbf(f01 - bf_hi(h0), f00 - bf_lo(h0));
    u32 l1 = packbf(f03 - bf_hi(h1), f02 - bf_lo(h1));
    u32 l2 = packbf(f11 - bf_hi(h2), f10 - bf_lo(h2));
    u32 l3 = packbf(f13 - bf_hi(h3), f12 - bf_lo(h3));
    g_bfragH[h][np][ks][l] = make_uint4(h0, h1, h2, h3);
    g_bfragL[h][np][ks][l] = make_uint4(l0, l1, l2, l3);
}

// ---------------- main kernel ----------------
struct __align__(16) PG {
    char  Areg[8704];          // Ahi[16][BROW], Alo at +4352; aliases:
                               //   Ys fp32 [16][132] (8448B); preamble scratch
    float A[NNODE][NNODE];     // normalized adjacency (symmetric)
    float Xat[OBSP][NNODE];    // (A@X) transposed
};

#define LOADROW8(dst, ptr) do { \
    const ulonglong2* _p = reinterpret_cast<const ulonglong2*>(ptr); \
    ulonglong2 _a = _p[0], _b = _p[1], _c = _p[2], _d = _p[3]; \
    dst[0]=_a.x; dst[1]=_a.y; dst[2]=_b.x; dst[3]=_b.y; \
    dst[4]=_c.x; dst[5]=_c.y; dst[6]=_d.x; dst[7]=_d.y; } while(0)

__global__ void __launch_bounds__(NTH, 4)
gcn_mma2(const float* __restrict__ obs, const float* __restrict__ act,
         const float* __restrict__ Q1W0, const float* __restrict__ Q1b0,
         const float* __restrict__ Q1b1, const float* __restrict__ Q1W2,
         const float* __restrict__ Q1b2,
         const float* __restrict__ Q2W0, const float* __restrict__ Q2b0,
         const float* __restrict__ Q2b1, const float* __restrict__ Q2W2,
         const float* __restrict__ Q2b2,
         float* __restrict__ out)
{
    __shared__ PG pg[GPB];
    const int tid  = threadIdx.x;
    const int warp = tid >> 5;
    const int lane = tid & 31;
    PG& P = pg[warp];
    const int g = blockIdx.x * GPB + warp;

    const u32 GAhi = smem_u32(P.Areg);
    const u32 GAlo = GAhi + 4352;
    float* Ys = reinterpret_cast<float*>(P.Areg);   // [16][132] fp32, aliases A tiles

    // ---- per-graph preamble (warp-private; scratch inside Areg)
    {
        float* Xt   = reinterpret_cast<float*>(P.Areg);
        float* lx   = Xt + 160;
        float* ly   = Xt + 176;
        float* dinv = Xt + 192;
        const float* ob = obs + (size_t)g * (NNODE * OBSP);
        #pragma unroll
        for (int r = 0; r < 5; r++) {
            int idx = lane + 32 * r;
            float v = ob[idx];
            int n = idx / OBSP, k = idx - n * OBSP;
            if (k == 0)      lx[n] = v;
            else if (k == 1) ly[n] = v;
            else             Xt[(k - 2) * NNODE + n] = v;
        }
        float v = act[(size_t)g * (NNODE * 2) + lane];
        Xt[(8 + (lane & 1)) * NNODE + (lane >> 1)] = v;
        __syncwarp();
        #pragma unroll
        for (int r = 0; r < 8; r++) {
            int e = lane * 8 + r, i = e >> 4, j = e & 15;
            float dx = lx[i] - lx[j], dy = ly[i] - ly[j];
            P.A[i][j] = expf(-sqrtf(dx * dx + dy * dy));
        }
        __syncwarp();
        if (lane < NNODE) {
            float s = 0.f;
            #pragma unroll
            for (int j = 0; j < NNODE; j++) s += P.A[j][lane];
            dinv[lane] = rsqrtf(s);               // deg >= 1 (self loop)
        }
        __syncwarp();
        #pragma unroll
        for (int r = 0; r < 8; r++) {
            int e = lane * 8 + r, i = e >> 4, j = e & 15;
            P.A[i][j] *= dinv[i] * dinv[j];
        }
        __syncwarp();
        #pragma unroll
        for (int r = 0; r < 5; r++) {
            int idx = lane + 32 * r;              // 160 = 16 x 10
            int i = idx / OBSP, k = idx - i * OBSP;
            float s = 0.f;
            #pragma unroll
            for (int j = 0; j < NNODE; j++) s = fmaf(P.A[i][j], Xt[k * NNODE + j], s);
            P.Xat[k][i] = s;
        }
        __syncwarp();
    }

    #pragma unroll 1
    for (int q = 0; q < 2; q++) {
        const float* W0 = q ? Q2W0 : Q1W0;
        const float* B0 = q ? Q2b0 : Q1b0;
        const float* B1 = q ? Q2b1 : Q1b1;
        const float* W2 = q ? Q2W2 : Q1W2;
        const float* B2 = q ? Q2b2 : Q1b2;

        // ==== GEMM0 (scalar fp32): y0 = Xa @ W0; relu(+b0) -> Ahi/Alo (bf16 split)
        {
            ull acc[32];
            #pragma unroll
            for (int p = 0; p < 32; p++) acc[p] = 0ull;
            #pragma unroll
            for (int k = 0; k < OBSP; k++) {
                float4 w4 = __ldg(reinterpret_cast<const float4*>(W0 + k * HID) + lane);
                ull row[8]; LOADROW8(row, &P.Xat[k][0]);
                ull wd;
                wd = pk2(w4.x, w4.x);
                #pragma unroll
                for (int m = 0; m < 8; m++) ffma2(acc[m],      row[m], wd);
                wd = pk2(w4.y, w4.y);
                #pragma unroll
                for (int m = 0; m < 8; m++) ffma2(acc[8 + m],  row[m], wd);
                wd = pk2(w4.z, w4.z);
                #pragma unroll
                for (int m = 0; m < 8; m++) ffma2(acc[16 + m], row[m], wd);
                wd = pk2(w4.w, w4.w);
                #pragma unroll
                for (int m = 0; m < 8; m++) ffma2(acc[24 + m], row[m], wd);
            }
            __syncwarp();   // prior-phase Ys reads (q==1) done before overwrite
            float4 b0v = __ldg(reinterpret_cast<const float4*>(B0) + lane);
            float bc[4] = {b0v.x, b0v.y, b0v.z, b0v.w};
            #pragma unroll
            for (int m = 0; m < 8; m++) {
                float va[4], vb[4];
                #pragma unroll
                for (int c = 0; c < 4; c++) upk2(acc[c * 8 + m], va[c], vb[c]);
                #pragma unroll
                for (int rr = 0; rr < 2; rr++) {
                    const float* v = rr ? vb : va;
                    int row = 2 * m + rr;
                    float h0 = fmaxf(v[0] + bc[0], 0.f), h1 = fmaxf(v[1] + bc[1], 0.f);
                    float h2 = fmaxf(v[2] + bc[2], 0.f), h3 = fmaxf(v[3] + bc[3], 0.f);
                    u32 p0 = packbf(h1, h0), p1 = packbf(h3, h2);
                    u32 q0 = packbf(h1 - bf_hi(p0), h0 - bf_lo(p0));
                    u32 q1 = packbf(h3 - bf_hi(p1), h2 - bf_lo(p1));
                    *reinterpret_cast<uint2*>(P.Areg + row * BROW + lane * 8)
                        = make_uint2(p0, p1);
                    *reinterpret_cast<uint2*>(P.Areg + 4352 + row * BROW + lane * 8)
                        = make_uint2(q0, q1);
                }
            }
        }
        __syncwarp();

        // ==== GEMM1 (tensor): y1 = h0 @ W1, 3-term bf16 split, B frags from gmem
        {
            u32 ah[8][4], al[8][4];
            const u32 arow = (u32)(lane & 15) * BROW + (u32)(lane >> 4) * 16;
            #pragma unroll
            for (int ks = 0; ks < 8; ks++) {
                LDSM_X4(ah[ks], GAhi + arow + ks * 32);
                LDSM_X4(al[ks], GAlo + arow + ks * 32);
            }
            __syncwarp();   // all A frags in regs before Ys overwrites the tiles
            const int gid = lane >> 2, tig = lane & 3;
            const uint4* BH = &g_bfragH[q][0][0][lane];
            const uint4* BL = &g_bfragL[q][0][0][lane];

            // pass 1: (Ah + Al) x Bh  -> Ys
            #pragma unroll 1
            for (int np = 0; np < 8; np++) {
                float d0[4] = {0,0,0,0}, d1[4] = {0,0,0,0};
                #pragma unroll
                for (int ks = 0; ks < 8; ks++) {
                    uint4 v = __ldg(BH + (np * 8 + ks) * 32);
                    MMA_BF16(d0, ah[ks], v.x, v.y);
                    MMA_BF16(d0, al[ks], v.x, v.y);
                    MMA_BF16(d1, ah[ks], v.z, v.w);
                    MMA_BF16(d1, al[ks], v.z, v.w);
                }
                #pragma unroll
                for (int t2 = 0; t2 < 2; t2++) {
                    float* d = t2 ? d1 : d0;
                    int col = 16 * np + 8 * t2 + 2 * tig;
                    *reinterpret_cast<float2*>(&Ys[gid * 132 + col])
                        = make_float2(d[0], d[1]);
                    *reinterpret_cast<float2*>(&Ys[(gid + 8) * 132 + col])
                        = make_float2(d[2], d[3]);
                }
            }
            // pass 2: Ah x Bl  -> Ys +=   (same-thread addresses: program order ok)
            #pragma unroll 1
            for (int np = 0; np < 8; np++) {
                float d0[4] = {0,0,0,0}, d1[4] = {0,0,0,0};
                #pragma unroll
                for (int ks = 0; ks < 8; ks++) {
                    uint4 v = __ldg(BL + (np * 8 + ks) * 32);
                    MMA_BF16(d0, ah[ks], v.x, v.y);
                    MMA_BF16(d1, ah[ks], v.z, v.w);
                }
                #pragma unroll
                for (int t2 = 0; t2 < 2; t2++) {
                    float* d = t2 ? d1 : d0;
                    int col = 16 * np + 8 * t2 + 2 * tig;
                    float2* p0 = reinterpret_cast<float2*>(&Ys[gid * 132 + col]);
                    float2* p1 = reinterpret_cast<float2*>(&Ys[(gid + 8) * 132 + col]);
                    float2 o0 = *p0, o1 = *p1;
                    *p0 = make_float2(o0.x + d[0], o0.y + d[1]);
                    *p1 = make_float2(o1.x + d[2], o1.y + d[3]);
                }
            }
        }
        __syncwarp();   // cross-lane Ys visibility for agg1

        // ==== agg1 = A @ y1; relu(+b1); fused layer-2 dot; reduce; final agg
        {
            ull acc2[32];
            #pragma unroll
            for (int p = 0; p < 32; p++) acc2[p] = 0ull;
            #pragma unroll 4
            for (int j = 0; j < NNODE; j++) {
                float4 y4 = *reinterpret_cast<const float4*>(&Ys[j * 132 + 4 * lane]);
                ull ar[8]; LOADROW8(ar, &P.A[j][0]);
                ull yd;
                yd = pk2(y4.x, y4.x);
                #pragma unroll
                for (int m = 0; m < 8; m++) ffma2(acc2[m],      ar[m], yd);
                yd = pk2(y4.y, y4.y);
                #pragma unroll
                for (int m = 0; m < 8; m++) ffma2(acc2[8 + m],  ar[m], yd);
                yd = pk2(y4.z, y4.z);
                #pragma unroll
                for (int m = 0; m < 8; m++) ffma2(acc2[16 + m], ar[m], yd);
                yd = pk2(y4.w, y4.w);
                #pragma unroll
                for (int m = 0; m < 8; m++) ffma2(acc2[24 + m], ar[m], yd);
            }
            ull part[8];
            #pragma unroll
            for (int m = 0; m < 8; m++) part[m] = 0ull;
            {
                float4 b1v = __ldg(reinterpret_cast<const float4*>(B1) + lane);
                float4 w2v = __ldg(reinterpret_cast<const float4*>(W2) + lane);
                float bc[4] = {b1v.x, b1v.y, b1v.z, b1v.w};
                float wc[4] = {w2v.x, w2v.y, w2v.z, w2v.w};
                #pragma unroll
                for (int c = 0; c < 4; c++) {
                    ull w2d = pk2(wc[c], wc[c]);
                    #pragma unroll
                    for (int m = 0; m < 8; m++) {
                        float lo, hi; upk2(acc2[c * 8 + m], lo, hi);
                        lo = fmaxf(lo + bc[c], 0.f);
                        hi = fmaxf(hi + bc[c], 0.f);
                        ffma2(part[m], pk2(lo, hi), w2d);
                    }
                }
            }
            #pragma unroll
            for (int off = 16; off > 0; off >>= 1) {
                #pragma unroll
                for (int m = 0; m < 8; m++) {
                    ull o = __shfl_xor_sync(0xffffffffu, part[m], off);
                    add2(part[m], o);
                }
            }
            if (lane < NNODE) {
                float y2[16];
                #pragma unroll
                for (int m = 0; m < 8; m++) upk2(part[m], y2[2 * m], y2[2 * m + 1]);
                float o = __ldg(B2);
                #pragma unroll
                for (int j = 0; j < NNODE; j++)
                    o = fmaf(P.A[j][lane], y2[j], o);
                out[(size_t)q * BSZ * NNODE + (size_t)g * NNODE + lane] = o;
            }
        }
        __syncwarp();   // Ys dead before next head's epilogue overwrites Areg
    }
}

extern "C" void kernel_launch(void* const* d_in, const int* in_sizes, int n_in,
                              void* d_out, int out_size)
{
    (void)in_sizes; (void)n_in; (void)out_size;
    prep_bfrag<<<16, 256>>>((const float*)d_in[4], (const float*)d_in[10]);
    gcn_mma2<<<BSZ / GPB, NTH>>>(
        (const float*)d_in[0],  (const float*)d_in[1],
        (const float*)d_in[2],  (const float*)d_in[3],   // Q1W0, Q1b0
        (const float*)d_in[5],                            // Q1b1
        (const float*)d_in[6],  (const float*)d_in[7],   // Q1W2, Q1b2
        (const float*)d_in[8],  (const float*)d_in[9],   // Q2W0, Q2b0
        (const float*)d_in[11],                           // Q2b1
        (const float*)d_in[12], (const float*)d_in[13],  // Q2W2, Q2b2
        (float*)d_out);
}